// round 17
// baseline (speedup 1.0000x reference)
#include <cuda_runtime.h>
#include <cuda_bf16.h>
#include <cmath>

// Fractional LIF SNN — frozen numeric contract (validated R5-R15, rel_err 2e-6):
//   * w_sh via f32 powf (libdevice __nv_powf, matches XLA-GPU)
//   * I_h: per-output single f32 accumulator, fmaf chain, k strictly ascending
//     (fma.rn.f32x2: each 64-bit lane is exactly that chain)
//   * mem sums: ascending-s f32 fmaf chains (hidden AND output)
//   * I_o: exact sum of selected f32 weights (spk in {0,1}), rounded once
//   * elementwise recurrence ops in reference f32 order
// R16 GEMM (resubmitted after infra failure): R8's proven shape (128x128
// tile, 256 threads, 8m x 8n, plain smem, grid 128) with BK 16 -> 32: 24
// sync boundaries instead of 49 (sync drain was ~23 us of R8's 78.4),
// dynamic smem 67.6 KB. Chain order unchanged -> bit-identical outputs.

#define B_DIM   64
#define T_DIM   64
#define NIN     784
#define NHID    512
#define NOUT    10

__device__ float    g_I[B_DIM * T_DIM * NHID];    // 8 MB hidden currents
__device__ unsigned g_spk[B_DIM * T_DIM * 16];    // 256 KB spike bitmasks

// ---------------------------------------------------------------------------
__device__ __forceinline__ unsigned long long ffma2(unsigned long long a,
                                                    unsigned long long b,
                                                    unsigned long long c) {
    unsigned long long d;
    asm("fma.rn.f32x2 %0, %1, %2, %3;" : "=l"(d) : "l"(a), "l"(b), "l"(c));
    return d;
}
__device__ __forceinline__ unsigned long long pack2(float x) {
    unsigned long long d;
    asm("mov.b64 %0, {%1, %1};" : "=l"(d) : "f"(x));
    return d;
}

// ---------------------------------------------------------------------------
// GEMM: C[m, n] = seqchain_k( A[m,k]*W[n,k] ) + bias[n]
// M = 4096, K = 784, N = 512.  Tile 128x128x32, 256 threads, 8m x 8n per
// thread (8 n as 4 packed f32x2), double-buffered DYNAMIC smem (67.6 KB),
// grid (32, 4) = 128 blocks.  K = 784 = 24*32 + 16: 24 full tiles + one
// 16-wide tail tile, all in ascending k -> bit-identical chain.
// ---------------------------------------------------------------------------
#define BM 128
#define BN 128
#define BK 32
#define STRIDE (BM + 4)   // 132 floats per k-row (16B-aligned)
#define GEMM_SMEM_BYTES (2 * (2 * BK * STRIDE) * 4)   // As + Ws

__global__ void __launch_bounds__(256, 1)
snn_gemm(const float* __restrict__ A, const float* __restrict__ W,
         const float* __restrict__ bias, float* __restrict__ C) {
    extern __shared__ float smem[];
    float (*As)[BK][STRIDE] = (float (*)[BK][STRIDE])smem;
    float (*Ws)[BK][STRIDE] = (float (*)[BK][STRIDE])(smem + 2 * BK * STRIDE);

    const int tid = threadIdx.x;
    const int tx  = tid & 15;        // n-group 0..15 (8 n: 2tx + 32j)
    const int ty  = tid >> 4;        // m-group 0..15 (8 m: 8ty..8ty+7)
    const int m_blk = blockIdx.x * BM;
    const int n_blk = blockIdx.y * BN;

    // loaders: 128 rows x 32 k / 256 thr = 16 floats (4 float4) per matrix
    const int row = tid >> 1;            // 0..127
    const int kq  = (tid & 1) * 16;      // 0 or 16

    const float* Ap = A + (size_t)(m_blk + row) * NIN + kq;
    const float* Wp = W + (size_t)(n_blk + row) * NIN + kq;

    float4 ra[4], rw[4];

    const int NKT = NIN / BK;            // 24 full tiles (tail = 16)

    // prologue: tile 0
#pragma unroll
    for (int q = 0; q < 4; q++) {
        ra[q] = *(const float4*)(Ap + 4 * q);
        rw[q] = *(const float4*)(Wp + 4 * q);
    }
#pragma unroll
    for (int q = 0; q < 4; q++) {
        As[0][kq + 4 * q + 0][row] = ra[q].x; As[0][kq + 4 * q + 1][row] = ra[q].y;
        As[0][kq + 4 * q + 2][row] = ra[q].z; As[0][kq + 4 * q + 3][row] = ra[q].w;
        Ws[0][kq + 4 * q + 0][row] = rw[q].x; Ws[0][kq + 4 * q + 1][row] = rw[q].y;
        Ws[0][kq + 4 * q + 2][row] = rw[q].z; Ws[0][kq + 4 * q + 3][row] = rw[q].w;
    }
    __syncthreads();

    unsigned long long acc[8][4];
#pragma unroll
    for (int m = 0; m < 8; m++)
#pragma unroll
        for (int j = 0; j < 4; j++) acc[m][j] = 0ULL;

    for (int kt = 0; kt < NKT; kt++) {
        const int cur = kt & 1;
        const bool last_full = (kt == NKT - 1);
        if (!last_full) {
#pragma unroll
            for (int q = 0; q < 4; q++) {
                ra[q] = *(const float4*)(Ap + (kt + 1) * BK + 4 * q);
                rw[q] = *(const float4*)(Wp + (kt + 1) * BK + 4 * q);
            }
        } else if (kq == 0) {
            // tail tile: only 16 k-columns; threads with kq==0 load them
#pragma unroll
            for (int q = 0; q < 4; q++) {
                ra[q] = *(const float4*)(Ap + NKT * BK + 4 * q);
                rw[q] = *(const float4*)(Wp + NKT * BK + 4 * q);
            }
        }
#pragma unroll
        for (int k = 0; k < BK; k++) {
            const float4 a01 = *(const float4*)&As[cur][k][ty * 8];
            const float4 a23 = *(const float4*)&As[cur][k][ty * 8 + 4];
            unsigned long long b2[4];
#pragma unroll
            for (int j = 0; j < 4; j++)
                b2[j] = *(const unsigned long long*)&Ws[cur][k][2 * tx + 32 * j];
            const float av[8] = {a01.x, a01.y, a01.z, a01.w,
                                 a23.x, a23.y, a23.z, a23.w};
#pragma unroll
            for (int m = 0; m < 8; m++) {
                const unsigned long long a2 = pack2(av[m]);
#pragma unroll
                for (int j = 0; j < 4; j++)
                    acc[m][j] = ffma2(a2, b2[j], acc[m][j]);
            }
        }
        {
            const int nxt = cur ^ 1;
            if (!last_full || kq == 0) {
#pragma unroll
                for (int q = 0; q < 4; q++) {
                    As[nxt][kq + 4 * q + 0][row] = ra[q].x;
                    As[nxt][kq + 4 * q + 1][row] = ra[q].y;
                    As[nxt][kq + 4 * q + 2][row] = ra[q].z;
                    As[nxt][kq + 4 * q + 3][row] = ra[q].w;
                    Ws[nxt][kq + 4 * q + 0][row] = rw[q].x;
                    Ws[nxt][kq + 4 * q + 1][row] = rw[q].y;
                    Ws[nxt][kq + 4 * q + 2][row] = rw[q].z;
                    Ws[nxt][kq + 4 * q + 3][row] = rw[q].w;
                }
            }
            __syncthreads();
        }
    }

    // tail: 16 k-columns in buffer NKT&1
    {
        const int cur = NKT & 1;
#pragma unroll
        for (int k = 0; k < 16; k++) {
            const float4 a01 = *(const float4*)&As[cur][k][ty * 8];
            const float4 a23 = *(const float4*)&As[cur][k][ty * 8 + 4];
            unsigned long long b2[4];
#pragma unroll
            for (int j = 0; j < 4; j++)
                b2[j] = *(const unsigned long long*)&Ws[cur][k][2 * tx + 32 * j];
            const float av[8] = {a01.x, a01.y, a01.z, a01.w,
                                 a23.x, a23.y, a23.z, a23.w};
#pragma unroll
            for (int m = 0; m < 8; m++) {
                const unsigned long long a2 = pack2(av[m]);
#pragma unroll
                for (int j = 0; j < 4; j++)
                    acc[m][j] = ffma2(a2, b2[j], acc[m][j]);
            }
        }
    }

    // epilogue: add bias, store float2 (lo -> col, hi -> col+1)
#pragma unroll
    for (int m = 0; m < 8; m++) {
        const int gm = m_blk + ty * 8 + m;
#pragma unroll
        for (int j = 0; j < 4; j++) {
            const int col = n_blk + 2 * tx + 32 * j;
            const unsigned long long v = acc[m][j];
            const float lo = __uint_as_float((unsigned)(v & 0xffffffffu));
            const float hi = __uint_as_float((unsigned)(v >> 32));
            float2 o;
            o.x = __fadd_rn(lo, bias[col]);
            o.y = __fadd_rn(hi, bias[col + 1]);
            *(float2*)&C[(size_t)gm * NHID + col] = o;
        }
    }
}

// ---------------------------------------------------------------------------
// Hidden recurrence: 128 blocks (2 per batch item) x 256 threads, no barriers
// in the time loop. Spikes exported as ballot bitmasks to g_spk.
// ---------------------------------------------------------------------------
__global__ void __launch_bounds__(256, 1)
snn_hidden(float scale) {
    const int b    = blockIdx.x >> 1;
    const int half = blockIdx.x & 1;
    const int tid  = threadIdx.x;
    const int lane = tid & 31;
    const int wid  = tid >> 5;
    const int h    = half * 256 + tid;

    __shared__ float w_sh[T_DIM];
    if (tid < T_DIM) {
        // f32 powf == libdevice __nv_powf == XLA-GPU lowering (verified exact)
        const float lagf = (float)tid;
        w_sh[tid] = (tid >= 2)
                        ? (powf(lagf, 0.8f) - powf(lagf - 1.0f, 0.8f))
                        : 0.0f;
    }
    __syncthreads();

    float D[T_DIM];
    float V = 0.0f;   // VRESET
    const float* Ibase = g_I + (size_t)(b * T_DIM) * NHID + h;
    float Ibuf[4];
    Ibuf[0] = Ibase[0];
    Ibuf[1] = Ibase[NHID];
    Ibuf[2] = Ibase[2 * NHID];
    Ibuf[3] = Ibase[3 * NHID];
    const float GLc = 0.025f;

#pragma unroll
    for (int t = 0; t < T_DIM; t++) {
        const float Icur = Ibuf[t & 3];
        if (t + 4 < T_DIM)
            Ibuf[t & 3] = Ibase[(size_t)(t + 4) * NHID];

        // hidden memory: f32 sequential fmaf chain, s ascending (frozen)
        float mem = 0.0f;
#pragma unroll
        for (int s = 0; s <= t - 2; s++)
            mem = fmaf(w_sh[t - s], D[s], mem);

        // Caputo L1 update, f32 ops in reference order
        const float f  = __fadd_rn(__fmul_rn(-GLc, V), Icur);
        const float g  = __fmul_rn(scale, f);
        const float h2 = __fmul_rn(g, 2.0f);
        const float Vn = __fsub_rn(__fadd_rn(V, h2), mem);
        const float Vp = (Vn > 1.0f) ? 0.0f : Vn;
        D[t] = __fsub_rn(Vp, V);
        V = Vp;

        const unsigned msk = __ballot_sync(0xffffffffu, Vn > 1.0f);
        if (lane == 0)
            g_spk[(b * T_DIM + t) * 16 + half * 8 + wid] = msk;
    }
}

// ---------------------------------------------------------------------------
// Output layer: 64 blocks (per batch item) x 512 threads.
//   phase 2: I_o via int64 fixed-point exact sums of selected W_o entries.
//   phase 3: output recurrence on 10 threads (frozen f32 chains).
// ---------------------------------------------------------------------------
#define FIX  9007199254740992.0   // 2^53

__global__ void __launch_bounds__(512, 1)
snn_out(const float* __restrict__ Wo, const float* __restrict__ bo,
        float* __restrict__ out, float scale) {
    const int b    = blockIdx.x;
    const int tid  = threadIdx.x;
    const int lane = tid & 31;
    const int wid  = tid >> 5;

    __shared__ float     w_sh[T_DIM];
    __shared__ unsigned  msk_sh[T_DIM][16];       // 4 KB
    __shared__ long long Wo_i[NOUT][NHID];        // 40 KB
    __shared__ float     Io_sh[T_DIM][NOUT];      // 2.5 KB

    if (tid < T_DIM) {
        const float lagf = (float)tid;
        w_sh[tid] = (tid >= 2)
                        ? (powf(lagf, 0.8f) - powf(lagf - 1.0f, 0.8f))
                        : 0.0f;
    }
    for (int i = tid; i < T_DIM * 16; i += 512)
        msk_sh[i >> 4][i & 15] = g_spk[b * T_DIM * 16 + i];
    for (int i = tid; i < NOUT * NHID; i += 512)
        Wo_i[i / NHID][i % NHID] = (long long)((double)Wo[i] * FIX);
    __syncthreads();

    // ---- phase 2: 640 selective sums; warp w handles t = 4w .. 4w+3 -------
    {
        const unsigned bit = 1u << lane;
        const int t0 = wid * 4;
#pragma unroll
        for (int tt = 0; tt < 4; tt++) {
            const int t = t0 + tt;
            unsigned m[16];
#pragma unroll
            for (int j = 0; j < 16; j++) m[j] = msk_sh[t][j];
            for (int o = 0; o < NOUT; o++) {
                long long s = 0;
#pragma unroll
                for (int j = 0; j < 16; j++)
                    if (m[j] & bit) s += Wo_i[o][j * 32 + lane];
#pragma unroll
                for (int off = 16; off > 0; off >>= 1)
                    s += __shfl_xor_sync(0xffffffffu, s, off);
                if (lane == 0)
                    Io_sh[t][o] =
                        __fadd_rn((float)((double)s * (1.0 / FIX)), bo[o]);
            }
        }
    }
    __syncthreads();

    // ---- phase 3: output recurrence (10 threads) --------------------------
    if (tid < NOUT) {
        const int o = tid;
        float Do[T_DIM];
        float Vo = 0.0f;
        const float GLc = 0.025f;

#pragma unroll
        for (int t = 0; t < T_DIM; t++) {
            // output memory: f32 sequential fmaf chain, s ascending (frozen)
            float mo = 0.0f;
#pragma unroll
            for (int s = 0; s <= t - 2; s++)
                mo = fmaf(w_sh[t - s], Do[s], mo);

            const float Io  = Io_sh[t][o];
            const float fo  = __fadd_rn(__fmul_rn(-GLc, Vo), Io);
            const float go  = __fmul_rn(scale, fo);
            const float ho  = __fmul_rn(go, 2.0f);
            const float Von = __fsub_rn(__fadd_rn(Vo, ho), mo);
            const float spko = (Von > 1.0f) ? 1.0f : 0.0f;
            const float Vop  = (Von > 1.0f) ? 0.0f : Von;
            Do[t] = __fsub_rn(Vop, Vo);
            Vo = Vop;

            const int idx = (t * B_DIM + b) * NOUT + o;
            out[idx] = spko;                               // spk_trace [T,B,O]
            out[T_DIM * B_DIM * NOUT + idx] = Vo;          // mem_trace [T,B,O]
        }
    }
}

// ---------------------------------------------------------------------------
extern "C" void kernel_launch(void* const* d_in, const int* in_sizes, int n_in,
                              void* d_out, int out_size) {
    const float* data = (const float*)d_in[0];   // [B,T,NIN]
    const float* W_h  = (const float*)d_in[1];   // [NHID,NIN]
    const float* b_h  = (const float*)d_in[2];   // [NHID]
    const float* W_o  = (const float*)d_in[3];   // [NOUT,NHID]
    const float* b_o  = (const float*)d_in[4];   // [NOUT]
    // d_in[5] = plotting (unused)

    float* I_ptr = nullptr;
    cudaGetSymbolAddress((void**)&I_ptr, g_I);   // no alloc; capture-safe

    // Opt in to >48KB dynamic smem (attribute set; capture-safe, idempotent).
    cudaFuncSetAttribute(snn_gemm,
                         cudaFuncAttributeMaxDynamicSharedMemorySize,
                         GEMM_SMEM_BYTES);

    const float scale = (float)(pow(0.1, 0.2) * tgamma(1.8));

    dim3 ggrid(B_DIM * T_DIM / BM, NHID / BN);   // (32, 4) = 128 blocks
    snn_gemm<<<ggrid, 256, GEMM_SMEM_BYTES>>>(data, W_h, b_h, I_ptr);
    snn_hidden<<<2 * B_DIM, 256>>>(scale);
    snn_out<<<B_DIM, 512>>>(W_o, b_o, (float*)d_out, scale);
}